// round 1
// baseline (speedup 1.0000x reference)
#include <cuda_runtime.h>
#include <math.h>

// ---------------- problem constants ----------------
#define BB 2
#define TT 4096
#define DD 1024
#define HH 16
#define DHH 64
#define FF 4096
#define KC 2048
#define LL 2
#define MR (BB * KC)   // 4096 active rows total

// ---------------- device scratch (static, allowed) ----------------
__device__ float g_logits[BB * TT];
__device__ int   g_sel[BB * KC];
__device__ float g_gate[BB * KC];
__device__ float g_h[MR * DD];
__device__ float g_y[MR * DD];
__device__ float g_qkv[MR * 3 * DD];
__device__ float g_ff[(size_t)MR * FF];
__device__ float g_scores[(size_t)BB * HH * KC * KC];  // 536 MB

// ---------------- router logits ----------------
__global__ void router_kernel(const float* __restrict__ x,
                              const float* __restrict__ w,
                              const float* __restrict__ b) {
    int token = blockIdx.x;  // 0..B*T-1
    const float* xr = x + (size_t)token * DD;
    float s = 0.f;
    for (int i = threadIdx.x; i < DD; i += blockDim.x) s += xr[i] * w[i];
    __shared__ float red[8];
    for (int o = 16; o > 0; o >>= 1) s += __shfl_down_sync(0xffffffffu, s, o);
    if ((threadIdx.x & 31) == 0) red[threadIdx.x >> 5] = s;
    __syncthreads();
    if (threadIdx.x < 32) {
        float v = (threadIdx.x < 8) ? red[threadIdx.x] : 0.f;
        for (int o = 4; o > 0; o >>= 1) v += __shfl_down_sync(0xffffffffu, v, o);
        if (threadIdx.x == 0) g_logits[token] = v + b[0];
    }
}

// ---------------- top-K via in-shared bitonic sort ----------------
__device__ __forceinline__ unsigned int ford(float f) {
    unsigned int u = __float_as_uint(f);
    return (u & 0x80000000u) ? ~u : (u | 0x80000000u);
}

__global__ void topk_kernel() {
    __shared__ unsigned long long s[TT];
    int b = blockIdx.x;
    const float* lg = g_logits + b * TT;
    for (int i = threadIdx.x; i < TT; i += blockDim.x) {
        unsigned long long key = ((unsigned long long)ford(lg[i]) << 32) | (unsigned int)i;
        s[i] = key;
    }
    __syncthreads();
    for (int k = 2; k <= TT; k <<= 1) {
        for (int j = k >> 1; j > 0; j >>= 1) {
            for (int i = threadIdx.x; i < TT; i += blockDim.x) {
                int ixj = i ^ j;
                if (ixj > i) {
                    bool up = ((i & k) == 0);
                    unsigned long long a = s[i], c = s[ixj];
                    if ((a > c) == up) { s[i] = c; s[ixj] = a; }
                }
            }
            __syncthreads();
        }
    }
    // ascending sort -> top-K at the tail
    for (int r = threadIdx.x; r < KC; r += blockDim.x) {
        unsigned long long key = s[TT - 1 - r];
        int idx = (int)(key & 0xffffffffu);
        g_sel[b * KC + r] = idx;
        float v = lg[idx];
        g_gate[b * KC + r] = 1.f / (1.f + expf(-v));
    }
}

// ---------------- gather active tokens ----------------
__global__ void gather_kernel(const float* __restrict__ x) {
    int row = blockIdx.x;  // b*KC + r
    int b = row / KC;
    int idx = g_sel[row];
    const float4* src = (const float4*)(x + ((size_t)b * TT + idx) * DD);
    float4* dst = (float4*)(g_h + (size_t)row * DD);
    for (int i = threadIdx.x; i < DD / 4; i += blockDim.x) dst[i] = src[i];
}

// ---------------- layernorm (per row of 1024, 256 threads) ----------------
__global__ void ln_kernel(const float* __restrict__ inp,
                          const float* __restrict__ w,
                          const float* __restrict__ bia,
                          float* __restrict__ out) {
    int row = blockIdx.x;
    const float* xr = inp + (size_t)row * DD;
    float vals[4];
    float s = 0.f, s2 = 0.f;
#pragma unroll
    for (int i = 0; i < 4; i++) {
        float v = xr[threadIdx.x + i * 256];
        vals[i] = v; s += v; s2 += v * v;
    }
    __shared__ float rs[8], rs2[8];
    for (int o = 16; o > 0; o >>= 1) {
        s  += __shfl_down_sync(0xffffffffu, s, o);
        s2 += __shfl_down_sync(0xffffffffu, s2, o);
    }
    if ((threadIdx.x & 31) == 0) { rs[threadIdx.x >> 5] = s; rs2[threadIdx.x >> 5] = s2; }
    __syncthreads();
    __shared__ float mu_s, rstd_s;
    if (threadIdx.x == 0) {
        float a = 0.f, c = 0.f;
        for (int i = 0; i < 8; i++) { a += rs[i]; c += rs2[i]; }
        float mu = a / DD;
        float var = c / DD - mu * mu;
        mu_s = mu; rstd_s = rsqrtf(var + 1e-5f);
    }
    __syncthreads();
    float mu = mu_s, rstd = rstd_s;
#pragma unroll
    for (int i = 0; i < 4; i++) {
        int c = threadIdx.x + i * 256;
        out[(size_t)row * DD + c] = (vals[i] - mu) * rstd * w[c] + bia[c];
    }
}

// ---------------- SGEMM NN: C = alpha*(A@B) [+ Cin], 128x128x8 tiles ----------------
// A [M,Kd] row-major (lda), B [Kd,N] row-major (ldb), C (ldc). M multiple of 128,
// Kd multiple of 8, N multiple of 64 (col-guarded at 128-tile granularity).
// Batch: z -> (zb = z/zdiv, zh = z%zdiv), offsets via (sX1, sX2).
__global__ void __launch_bounds__(256) sgemm_nn(
    const float* __restrict__ A, const float* __restrict__ B,
    const float* __restrict__ Cin, float* __restrict__ Cout,
    int N, int Kd, int lda, int ldb, int ldc,
    int zdiv, long long sA1, long long sA2, long long sB1, long long sB2,
    long long sC1, long long sC2, float alpha, int addC)
{
    int zb = blockIdx.z / zdiv, zh = blockIdx.z % zdiv;
    A    += (long long)zb * sA1 + (long long)zh * sA2;
    B    += (long long)zb * sB1 + (long long)zh * sB2;
    Cin  += (long long)zb * sC1 + (long long)zh * sC2;
    Cout += (long long)zb * sC1 + (long long)zh * sC2;

    int bm = blockIdx.y * 128;
    int bn = blockIdx.x * 128;

    __shared__ float As[8][132];
    __shared__ float Bs[8][128];

    int tid = threadIdx.x;
    int ty = tid >> 4, tx = tid & 15;
    int arow = tid >> 1, akq = (tid & 1) * 4;
    int brow = tid >> 5, bcol = (tid & 31) * 4;

    float acc[8][8];
#pragma unroll
    for (int i = 0; i < 8; i++)
#pragma unroll
        for (int j = 0; j < 8; j++) acc[i][j] = 0.f;

    for (int k0 = 0; k0 < Kd; k0 += 8) {
        float4 av = *(const float4*)(A + (long long)(bm + arow) * lda + k0 + akq);
        As[akq + 0][arow] = av.x; As[akq + 1][arow] = av.y;
        As[akq + 2][arow] = av.z; As[akq + 3][arow] = av.w;
        float4 bv = make_float4(0.f, 0.f, 0.f, 0.f);
        if (bn + bcol < N)
            bv = *(const float4*)(B + (long long)(k0 + brow) * ldb + bn + bcol);
        *(float4*)&Bs[brow][bcol] = bv;
        __syncthreads();
#pragma unroll
        for (int kk = 0; kk < 8; kk++) {
            float a[8], bb[8];
            *(float4*)&a[0]  = *(const float4*)&As[kk][ty * 8];
            *(float4*)&a[4]  = *(const float4*)&As[kk][ty * 8 + 4];
            *(float4*)&bb[0] = *(const float4*)&Bs[kk][tx * 8];
            *(float4*)&bb[4] = *(const float4*)&Bs[kk][tx * 8 + 4];
#pragma unroll
            for (int i = 0; i < 8; i++)
#pragma unroll
                for (int j = 0; j < 8; j++) acc[i][j] += a[i] * bb[j];
        }
        __syncthreads();
    }
#pragma unroll
    for (int i = 0; i < 8; i++) {
        int m = bm + ty * 8 + i;
#pragma unroll
        for (int j = 0; j < 8; j += 4) {
            int n = bn + tx * 8 + j;
            if (n < N) {
                float4 v;
                v.x = acc[i][j] * alpha;   v.y = acc[i][j + 1] * alpha;
                v.z = acc[i][j + 2] * alpha; v.w = acc[i][j + 3] * alpha;
                if (addC) {
                    float4 ci = *(const float4*)(Cin + (long long)m * ldc + n);
                    v.x += ci.x; v.y += ci.y; v.z += ci.z; v.w += ci.w;
                }
                *(float4*)(Cout + (long long)m * ldc + n) = v;
            }
        }
    }
}

// ---------------- SGEMM NT: C = alpha*(A @ B^T), both [.,Kd] row-major ----------------
// M, N multiples of 128, Kd multiple of 8.
__global__ void __launch_bounds__(256) sgemm_nt(
    const float* __restrict__ A, const float* __restrict__ B,
    float* __restrict__ Cout,
    int Kd, int lda, int ldb, int ldc,
    int zdiv, long long sA1, long long sA2, long long sB1, long long sB2,
    long long sC1, long long sC2, float alpha)
{
    int zb = blockIdx.z / zdiv, zh = blockIdx.z % zdiv;
    A    += (long long)zb * sA1 + (long long)zh * sA2;
    B    += (long long)zb * sB1 + (long long)zh * sB2;
    Cout += (long long)zb * sC1 + (long long)zh * sC2;

    int bm = blockIdx.y * 128;
    int bn = blockIdx.x * 128;

    __shared__ float As[8][132];
    __shared__ float Bs[8][132];

    int tid = threadIdx.x;
    int ty = tid >> 4, tx = tid & 15;
    int row = tid >> 1, kq = (tid & 1) * 4;

    float acc[8][8];
#pragma unroll
    for (int i = 0; i < 8; i++)
#pragma unroll
        for (int j = 0; j < 8; j++) acc[i][j] = 0.f;

    for (int k0 = 0; k0 < Kd; k0 += 8) {
        float4 av = *(const float4*)(A + (long long)(bm + row) * lda + k0 + kq);
        As[kq + 0][row] = av.x; As[kq + 1][row] = av.y;
        As[kq + 2][row] = av.z; As[kq + 3][row] = av.w;
        float4 bv = *(const float4*)(B + (long long)(bn + row) * ldb + k0 + kq);
        Bs[kq + 0][row] = bv.x; Bs[kq + 1][row] = bv.y;
        Bs[kq + 2][row] = bv.z; Bs[kq + 3][row] = bv.w;
        __syncthreads();
#pragma unroll
        for (int kk = 0; kk < 8; kk++) {
            float a[8], bb[8];
            *(float4*)&a[0]  = *(const float4*)&As[kk][ty * 8];
            *(float4*)&a[4]  = *(const float4*)&As[kk][ty * 8 + 4];
            *(float4*)&bb[0] = *(const float4*)&Bs[kk][tx * 8];
            *(float4*)&bb[4] = *(const float4*)&Bs[kk][tx * 8 + 4];
#pragma unroll
            for (int i = 0; i < 8; i++)
#pragma unroll
                for (int j = 0; j < 8; j++) acc[i][j] += a[i] * bb[j];
        }
        __syncthreads();
    }
#pragma unroll
    for (int i = 0; i < 8; i++) {
        int m = bm + ty * 8 + i;
#pragma unroll
        for (int j = 0; j < 8; j += 4) {
            int n = bn + tx * 8 + j;
            float4 v;
            v.x = acc[i][j] * alpha;   v.y = acc[i][j + 1] * alpha;
            v.z = acc[i][j + 2] * alpha; v.w = acc[i][j + 3] * alpha;
            *(float4*)(Cout + (long long)m * ldc + n) = v;
        }
    }
}

// ---------------- row softmax over scores rows of length KC ----------------
__global__ void softmax_kernel() {
    size_t row = blockIdx.x;  // B*H*KC rows
    float* p = g_scores + row * KC;
    int tid = threadIdx.x;  // 256
    float vals[8];
    float mx = -1e30f;
#pragma unroll
    for (int i = 0; i < 8; i++) { float v = p[tid + i * 256]; vals[i] = v; mx = fmaxf(mx, v); }
    __shared__ float red[8];
    for (int o = 16; o > 0; o >>= 1) mx = fmaxf(mx, __shfl_xor_sync(0xffffffffu, mx, o));
    if ((tid & 31) == 0) red[tid >> 5] = mx;
    __syncthreads();
    __shared__ float m_s, s_s;
    if (tid == 0) {
        float m = red[0];
        for (int i = 1; i < 8; i++) m = fmaxf(m, red[i]);
        m_s = m;
    }
    __syncthreads();
    mx = m_s;
    float s = 0.f;
#pragma unroll
    for (int i = 0; i < 8; i++) { vals[i] = expf(vals[i] - mx); s += vals[i]; }
    for (int o = 16; o > 0; o >>= 1) s += __shfl_down_sync(0xffffffffu, s, o);
    if ((tid & 31) == 0) red[tid >> 5] = s;
    __syncthreads();
    if (tid == 0) {
        float a = 0.f;
        for (int i = 0; i < 8; i++) a += red[i];
        s_s = a;
    }
    __syncthreads();
    float inv = 1.f / s_s;
#pragma unroll
    for (int i = 0; i < 8; i++) p[tid + i * 256] = vals[i] * inv;
}

// ---------------- gelu (tanh approximation, jax default) ----------------
__global__ void gelu_kernel(float* __restrict__ p) {
    size_t i = (size_t)blockIdx.x * blockDim.x + threadIdx.x;
    float x = p[i];
    const float c = 0.7978845608028654f;  // sqrt(2/pi)
    float t = tanhf(c * (x + 0.044715f * x * x * x));
    p[i] = 0.5f * x * (1.f + t);
}

// ---------------- gated scatter-add (unique indices per batch) ----------------
__global__ void scatter_kernel(float* __restrict__ out) {
    int row = blockIdx.x;  // b*KC + r
    int b = row / KC;
    int idx = g_sel[row];
    float g = g_gate[row];
    float4* dst = (float4*)(out + ((size_t)b * TT + idx) * DD);
    const float4* src = (const float4*)(g_h + (size_t)row * DD);
    for (int i = threadIdx.x; i < DD / 4; i += blockDim.x) {
        float4 d = dst[i], s = src[i];
        d.x += g * s.x; d.y += g * s.y; d.z += g * s.z; d.w += g * s.w;
        dst[i] = d;
    }
}

// ---------------- host launcher ----------------
extern "C" void kernel_launch(void* const* d_in, const int* in_sizes, int n_in,
                              void* d_out, int out_size) {
    const float* x        = (const float*)d_in[0];
    const float* router_w = (const float*)d_in[1];
    const float* router_b = (const float*)d_in[2];
    const float* ln1_w    = (const float*)d_in[3];
    const float* ln1_b    = (const float*)d_in[4];
    const float* wqkv     = (const float*)d_in[5];
    const float* wo       = (const float*)d_in[6];
    const float* ln2_w    = (const float*)d_in[7];
    const float* ln2_b    = (const float*)d_in[8];
    const float* w1       = (const float*)d_in[9];
    const float* w2       = (const float*)d_in[10];
    float* out = (float*)d_out;

    float *p_h, *p_y, *p_qkv, *p_ff, *p_scores;
    cudaGetSymbolAddress((void**)&p_h, g_h);
    cudaGetSymbolAddress((void**)&p_y, g_y);
    cudaGetSymbolAddress((void**)&p_qkv, g_qkv);
    cudaGetSymbolAddress((void**)&p_ff, g_ff);
    cudaGetSymbolAddress((void**)&p_scores, g_scores);

    router_kernel<<<BB * TT, 256>>>(x, router_w, router_b);
    topk_kernel<<<BB, 1024>>>();
    gather_kernel<<<MR, 256>>>(x);

    const long long qkvB = (long long)KC * 3 * DD;  // per-batch stride in qkv buffer

    for (int l = 0; l < LL; l++) {
        // --- attention sub-block ---
        ln_kernel<<<MR, 256>>>(p_h, ln1_w + l * DD, ln1_b + l * DD, p_y);

        sgemm_nn<<<dim3(3 * DD / 128, MR / 128, 1), 256>>>(
            p_y, wqkv + (size_t)l * DD * 3 * DD, p_qkv, p_qkv,
            3 * DD, DD, DD, 3 * DD, 3 * DD,
            1, 0, 0, 0, 0, 0, 0, 1.f, 0);

        // S = Q @ K^T / sqrt(DH), batched over (b, h)
        sgemm_nt<<<dim3(KC / 128, KC / 128, BB * HH), 256>>>(
            p_qkv /*Q*/, p_qkv + DD /*K*/, p_scores,
            DHH, 3 * DD, 3 * DD, KC,
            HH, qkvB, DHH, qkvB, DHH,
            (long long)HH * KC * KC, (long long)KC * KC, 0.125f);

        softmax_kernel<<<BB * HH * KC, 256>>>();

        // O = P @ V  -> written head-sliced into p_y  (N = 64 per head)
        sgemm_nn<<<dim3(1, KC / 128, BB * HH), 256>>>(
            p_scores, p_qkv + 2 * DD /*V*/, p_y, p_y,
            DHH, KC, KC, 3 * DD, DD,
            HH, (long long)HH * KC * KC, (long long)KC * KC,
            qkvB, DHH,
            (long long)KC * DD, DHH, 1.f, 0);

        // h += O @ Wo
        sgemm_nn<<<dim3(DD / 128, MR / 128, 1), 256>>>(
            p_y, wo + (size_t)l * DD * DD, p_h, p_h,
            DD, DD, DD, DD, DD,
            1, 0, 0, 0, 0, 0, 0, 1.f, 1);

        // --- MLP sub-block ---
        ln_kernel<<<MR, 256>>>(p_h, ln2_w + l * DD, ln2_b + l * DD, p_y);

        sgemm_nn<<<dim3(FF / 128, MR / 128, 1), 256>>>(
            p_y, w1 + (size_t)l * DD * FF, p_ff, p_ff,
            FF, DD, DD, FF, FF,
            1, 0, 0, 0, 0, 0, 0, 1.f, 0);

        gelu_kernel<<<(unsigned)(((size_t)MR * FF) / 256), 256>>>(p_ff);

        // h += gelu(ff) @ W2
        sgemm_nn<<<dim3(DD / 128, MR / 128, 1), 256>>>(
            p_ff, w2 + (size_t)l * FF * DD, p_h, p_h,
            DD, FF, FF, DD, DD,
            1, 0, 0, 0, 0, 0, 0, 1.f, 1);
    }

    // out = x ; out[b, sel] += gate * h
    cudaMemcpyAsync(out, x, (size_t)BB * TT * DD * sizeof(float),
                    cudaMemcpyDeviceToDevice, 0);
    scatter_kernel<<<MR, 256>>>(out);
}

// round 2
// speedup vs baseline: 2.5444x; 2.5444x over previous
#include <cuda_runtime.h>
#include <math.h>

// ---------------- problem constants ----------------
#define BB 2
#define TT 4096
#define DD 1024
#define HH 16
#define DHH 64
#define FF 4096
#define KC 2048
#define LL 2
#define MR (BB * KC)   // 4096 active rows total

// ---------------- device scratch (static, allowed) ----------------
__device__ float g_logits[BB * TT];
__device__ int   g_sel[BB * KC];
__device__ float g_gate[BB * KC];
__device__ float g_h[MR * DD];
__device__ float g_y[MR * DD];
__device__ float g_qkv[MR * 3 * DD];
__device__ float g_ff[(size_t)MR * FF];
__device__ float g_scores[(size_t)BB * HH * KC * KC];  // 536 MB

// ---------------- router logits ----------------
__global__ void router_kernel(const float* __restrict__ x,
                              const float* __restrict__ w,
                              const float* __restrict__ b) {
    int token = blockIdx.x;
    const float* xr = x + (size_t)token * DD;
    float s = 0.f;
    for (int i = threadIdx.x; i < DD; i += blockDim.x) s += xr[i] * w[i];
    __shared__ float red[8];
    for (int o = 16; o > 0; o >>= 1) s += __shfl_down_sync(0xffffffffu, s, o);
    if ((threadIdx.x & 31) == 0) red[threadIdx.x >> 5] = s;
    __syncthreads();
    if (threadIdx.x < 32) {
        float v = (threadIdx.x < 8) ? red[threadIdx.x] : 0.f;
        for (int o = 4; o > 0; o >>= 1) v += __shfl_down_sync(0xffffffffu, v, o);
        if (threadIdx.x == 0) g_logits[token] = v + b[0];
    }
}

// ---------------- top-K via in-shared bitonic sort ----------------
__device__ __forceinline__ unsigned int ford(float f) {
    unsigned int u = __float_as_uint(f);
    return (u & 0x80000000u) ? ~u : (u | 0x80000000u);
}

__global__ void topk_kernel() {
    __shared__ unsigned long long s[TT];
    int b = blockIdx.x;
    const float* lg = g_logits + b * TT;
    for (int i = threadIdx.x; i < TT; i += blockDim.x) {
        unsigned long long key = ((unsigned long long)ford(lg[i]) << 32) | (unsigned int)i;
        s[i] = key;
    }
    __syncthreads();
    for (int k = 2; k <= TT; k <<= 1) {
        for (int j = k >> 1; j > 0; j >>= 1) {
            for (int i = threadIdx.x; i < TT; i += blockDim.x) {
                int ixj = i ^ j;
                if (ixj > i) {
                    bool up = ((i & k) == 0);
                    unsigned long long a = s[i], c = s[ixj];
                    if ((a > c) == up) { s[i] = c; s[ixj] = a; }
                }
            }
            __syncthreads();
        }
    }
    for (int r = threadIdx.x; r < KC; r += blockDim.x) {
        unsigned long long key = s[TT - 1 - r];
        int idx = (int)(key & 0xffffffffu);
        g_sel[b * KC + r] = idx;
        float v = lg[idx];
        g_gate[b * KC + r] = 1.f / (1.f + expf(-v));
    }
}

// ---------------- gather active tokens ----------------
__global__ void gather_kernel(const float* __restrict__ x) {
    int row = blockIdx.x;
    int b = row / KC;
    int idx = g_sel[row];
    const float4* src = (const float4*)(x + ((size_t)b * TT + idx) * DD);
    float4* dst = (float4*)(g_h + (size_t)row * DD);
    for (int i = threadIdx.x; i < DD / 4; i += blockDim.x) dst[i] = src[i];
}

// ---------------- layernorm ----------------
__global__ void ln_kernel(const float* __restrict__ inp,
                          const float* __restrict__ w,
                          const float* __restrict__ bia,
                          float* __restrict__ out) {
    int row = blockIdx.x;
    const float* xr = inp + (size_t)row * DD;
    float vals[4];
    float s = 0.f, s2 = 0.f;
#pragma unroll
    for (int i = 0; i < 4; i++) {
        float v = xr[threadIdx.x + i * 256];
        vals[i] = v; s += v; s2 += v * v;
    }
    __shared__ float rs[8], rs2[8];
    for (int o = 16; o > 0; o >>= 1) {
        s  += __shfl_down_sync(0xffffffffu, s, o);
        s2 += __shfl_down_sync(0xffffffffu, s2, o);
    }
    if ((threadIdx.x & 31) == 0) { rs[threadIdx.x >> 5] = s; rs2[threadIdx.x >> 5] = s2; }
    __syncthreads();
    __shared__ float mu_s, rstd_s;
    if (threadIdx.x == 0) {
        float a = 0.f, c = 0.f;
        for (int i = 0; i < 8; i++) { a += rs[i]; c += rs2[i]; }
        float mu = a / DD;
        float var = c / DD - mu * mu;
        mu_s = mu; rstd_s = rsqrtf(var + 1e-5f);
    }
    __syncthreads();
    float mu = mu_s, rstd = rstd_s;
#pragma unroll
    for (int i = 0; i < 4; i++) {
        int c = threadIdx.x + i * 256;
        out[(size_t)row * DD + c] = (vals[i] - mu) * rstd * w[c] + bia[c];
    }
}

// ============================================================================
// TF32 tensor-core GEMM, CTA tile 128x128x32, 8 warps (2x4), warp tile 64x32.
// mma.sync.aligned.m16n8k8.row.col.f32.tf32.tf32.f32
// A [M,Kd] row-major. TRANSB=0: B [Kd,N] row-major. TRANSB=1: B [N,Kd] row-major.
// M multiple of 128, Kd multiple of 32, N multiple of 64 (cols guarded).
// ============================================================================

__device__ __forceinline__ unsigned cvt_tf32(float f) {
    unsigned u;
    asm("cvt.rna.tf32.f32 %0, %1;" : "=r"(u) : "f"(f));
    return u;
}
__device__ __forceinline__ uint4 cvt_tf32x4(float4 v) {
    uint4 u;
    u.x = cvt_tf32(v.x); u.y = cvt_tf32(v.y);
    u.z = cvt_tf32(v.z); u.w = cvt_tf32(v.w);
    return u;
}
__device__ __forceinline__ void ldsm_x4(unsigned* r, unsigned addr) {
    asm volatile("ldmatrix.sync.aligned.m8n8.x4.shared.b16 {%0,%1,%2,%3}, [%4];"
                 : "=r"(r[0]), "=r"(r[1]), "=r"(r[2]), "=r"(r[3]) : "r"(addr));
}
__device__ __forceinline__ void ldsm_x2(unsigned* r, unsigned addr) {
    asm volatile("ldmatrix.sync.aligned.m8n8.x2.shared.b16 {%0,%1}, [%2];"
                 : "=r"(r[0]), "=r"(r[1]) : "r"(addr));
}
__device__ __forceinline__ void mma_tf32(float* c, const unsigned* a, const unsigned* b) {
    asm volatile(
        "mma.sync.aligned.m16n8k8.row.col.f32.tf32.tf32.f32 "
        "{%0,%1,%2,%3}, {%4,%5,%6,%7}, {%8,%9}, {%0,%1,%2,%3};"
        : "+f"(c[0]), "+f"(c[1]), "+f"(c[2]), "+f"(c[3])
        : "r"(a[0]), "r"(a[1]), "r"(a[2]), "r"(a[3]), "r"(b[0]), "r"(b[1]));
}

template<bool TRANSB>
__global__ void __launch_bounds__(256, 1) tc_gemm(
    const float* __restrict__ A, const float* __restrict__ B,
    const float* __restrict__ Cin, float* __restrict__ Cout,
    int M, int N, int Kd, int lda, int ldb, int ldc,
    int zdiv, long long sA1, long long sA2, long long sB1, long long sB2,
    long long sC1, long long sC2, float alpha, int addC)
{
    __shared__ float As[128 * 36];   // [m][k], pitch 36 floats (k-tile 32 + pad)
    __shared__ float Bs[128 * 36];   // NN: [k][n] pitch 132 (fits 32*132); NT: [n][k] pitch 36

    int zb = blockIdx.z / zdiv, zh = blockIdx.z % zdiv;
    A    += (long long)zb * sA1 + (long long)zh * sA2;
    B    += (long long)zb * sB1 + (long long)zh * sB2;
    Cin  += (long long)zb * sC1 + (long long)zh * sC2;
    Cout += (long long)zb * sC1 + (long long)zh * sC2;

    int bm = blockIdx.y * 128;
    int bn = blockIdx.x * 128;

    int tid  = threadIdx.x;
    int lane = tid & 31;
    int warp = tid >> 5;
    int warpM = (warp >> 2) * 64;
    int warpN = (warp & 3) * 32;

    // staging thread mapping
    int aKq  = tid & 7;          // k-quad (4 floats)
    int aRow = tid >> 3;         // 0..31 (+32 per pass)  (A and NT-B)
    int bNq  = tid & 31;         // n-quad (NN-B)
    int bKr  = tid >> 5;         // 0..7 (+8 per pass)

    // ldmatrix per-lane addresses (byte, shared space)
    unsigned sAa = (unsigned)__cvta_generic_to_shared(As);
    unsigned sBa = (unsigned)__cvta_generic_to_shared(Bs);
    int lr = lane & 7, ls = (lane >> 3) & 1, lt = lane >> 4;
    unsigned addrA[4];
#pragma unroll
    for (int mt = 0; mt < 4; mt++)
        addrA[mt] = sAa + (unsigned)(((warpM + mt * 16 + lr + ls * 8) * 36 + lt * 4) * 4);
    unsigned addrB[4];
#pragma unroll
    for (int nt = 0; nt < 4; nt++)
        addrB[nt] = sBa + (unsigned)(((warpN + nt * 8 + lr) * 36 + ls * 4) * 4);

    float acc[4][4][4];
#pragma unroll
    for (int i = 0; i < 4; i++)
#pragma unroll
        for (int j = 0; j < 4; j++)
#pragma unroll
            for (int q = 0; q < 4; q++) acc[i][j][q] = 0.f;

    float4 ra[4], rb[4];
    bool bColOK = TRANSB ? true : (bn + bNq * 4 < N);

    // ---- prologue: load tile 0 ----
#pragma unroll
    for (int p = 0; p < 4; p++)
        ra[p] = *(const float4*)(A + (long long)(bm + aRow + 32 * p) * lda + aKq * 4);
    if (TRANSB) {
#pragma unroll
        for (int p = 0; p < 4; p++)
            rb[p] = *(const float4*)(B + (long long)(bn + aRow + 32 * p) * ldb + aKq * 4);
    } else {
#pragma unroll
        for (int p = 0; p < 4; p++)
            rb[p] = bColOK ? *(const float4*)(B + (long long)(bKr + 8 * p) * ldb + bn + bNq * 4)
                           : make_float4(0.f, 0.f, 0.f, 0.f);
    }
#pragma unroll
    for (int p = 0; p < 4; p++)
        *(uint4*)&As[(aRow + 32 * p) * 36 + aKq * 4] = cvt_tf32x4(ra[p]);
    if (TRANSB) {
#pragma unroll
        for (int p = 0; p < 4; p++)
            *(uint4*)&Bs[(aRow + 32 * p) * 36 + aKq * 4] = cvt_tf32x4(rb[p]);
    } else {
#pragma unroll
        for (int p = 0; p < 4; p++)
            *(uint4*)&Bs[(bKr + 8 * p) * 132 + bNq * 4] = cvt_tf32x4(rb[p]);
    }
    __syncthreads();

    int kIters = Kd >> 5;
    for (int kt = 0; kt < kIters; kt++) {
        bool next = (kt + 1 < kIters);
        if (next) {
            int k0 = (kt + 1) * 32;
#pragma unroll
            for (int p = 0; p < 4; p++)
                ra[p] = *(const float4*)(A + (long long)(bm + aRow + 32 * p) * lda + k0 + aKq * 4);
            if (TRANSB) {
#pragma unroll
                for (int p = 0; p < 4; p++)
                    rb[p] = *(const float4*)(B + (long long)(bn + aRow + 32 * p) * ldb + k0 + aKq * 4);
            } else {
#pragma unroll
                for (int p = 0; p < 4; p++)
                    rb[p] = bColOK ? *(const float4*)(B + (long long)(k0 + bKr + 8 * p) * ldb + bn + bNq * 4)
                                   : make_float4(0.f, 0.f, 0.f, 0.f);
            }
        }

#pragma unroll
        for (int k8 = 0; k8 < 4; k8++) {
            unsigned aF[4][4];
#pragma unroll
            for (int mt = 0; mt < 4; mt++)
                ldsm_x4(aF[mt], addrA[mt] + k8 * 32);
            unsigned bF[4][2];
            if (TRANSB) {
#pragma unroll
                for (int nt = 0; nt < 4; nt++)
                    ldsm_x2(bF[nt], addrB[nt] + k8 * 32);
            } else {
                int c = lane & 3, grp = lane >> 2;
#pragma unroll
                for (int nt = 0; nt < 4; nt++) {
                    bF[nt][0] = __float_as_uint(Bs[(k8 * 8 + c) * 132 + warpN + nt * 8 + grp]);
                    bF[nt][1] = __float_as_uint(Bs[(k8 * 8 + c + 4) * 132 + warpN + nt * 8 + grp]);
                }
            }
#pragma unroll
            for (int mt = 0; mt < 4; mt++)
#pragma unroll
                for (int nt = 0; nt < 4; nt++)
                    mma_tf32(acc[mt][nt], aF[mt], bF[nt]);
        }

        if (next) {
            __syncthreads();
#pragma unroll
            for (int p = 0; p < 4; p++)
                *(uint4*)&As[(aRow + 32 * p) * 36 + aKq * 4] = cvt_tf32x4(ra[p]);
            if (TRANSB) {
#pragma unroll
                for (int p = 0; p < 4; p++)
                    *(uint4*)&Bs[(aRow + 32 * p) * 36 + aKq * 4] = cvt_tf32x4(rb[p]);
            } else {
#pragma unroll
                for (int p = 0; p < 4; p++)
                    *(uint4*)&Bs[(bKr + 8 * p) * 132 + bNq * 4] = cvt_tf32x4(rb[p]);
            }
            __syncthreads();
        }
    }

    // ---- epilogue ----
    int grp = lane >> 2, c2 = (lane & 3) * 2;
#pragma unroll
    for (int mt = 0; mt < 4; mt++) {
#pragma unroll
        for (int nt = 0; nt < 4; nt++) {
            int col = bn + warpN + nt * 8 + c2;
            if (col < N) {
                long long r0 = (long long)(bm + warpM + mt * 16 + grp) * ldc + col;
                long long r1 = r0 + 8LL * ldc;
                float2 v0 = make_float2(acc[mt][nt][0] * alpha, acc[mt][nt][1] * alpha);
                float2 v1 = make_float2(acc[mt][nt][2] * alpha, acc[mt][nt][3] * alpha);
                if (addC) {
                    float2 ci0 = *(const float2*)(Cin + r0);
                    float2 ci1 = *(const float2*)(Cin + r1);
                    v0.x += ci0.x; v0.y += ci0.y;
                    v1.x += ci1.x; v1.y += ci1.y;
                }
                *(float2*)(Cout + r0) = v0;
                *(float2*)(Cout + r1) = v1;
            }
        }
    }
}

// ---------------- row softmax over scores rows of length KC ----------------
__global__ void softmax_kernel() {
    size_t row = blockIdx.x;
    float* p = g_scores + row * KC;
    int tid = threadIdx.x;
    float vals[8];
    float mx = -1e30f;
#pragma unroll
    for (int i = 0; i < 8; i++) { float v = p[tid + i * 256]; vals[i] = v; mx = fmaxf(mx, v); }
    __shared__ float red[8];
    for (int o = 16; o > 0; o >>= 1) mx = fmaxf(mx, __shfl_xor_sync(0xffffffffu, mx, o));
    if ((tid & 31) == 0) red[tid >> 5] = mx;
    __syncthreads();
    __shared__ float m_s, s_s;
    if (tid == 0) {
        float m = red[0];
        for (int i = 1; i < 8; i++) m = fmaxf(m, red[i]);
        m_s = m;
    }
    __syncthreads();
    mx = m_s;
    float s = 0.f;
#pragma unroll
    for (int i = 0; i < 8; i++) { vals[i] = expf(vals[i] - mx); s += vals[i]; }
    for (int o = 16; o > 0; o >>= 1) s += __shfl_down_sync(0xffffffffu, s, o);
    if ((tid & 31) == 0) red[tid >> 5] = s;
    __syncthreads();
    if (tid == 0) {
        float a = 0.f;
        for (int i = 0; i < 8; i++) a += red[i];
        s_s = a;
    }
    __syncthreads();
    float inv = 1.f / s_s;
#pragma unroll
    for (int i = 0; i < 8; i++) p[tid + i * 256] = vals[i] * inv;
}

// ---------------- gelu (tanh approximation, jax default) ----------------
__global__ void gelu_kernel(float* __restrict__ p) {
    size_t i = (size_t)blockIdx.x * blockDim.x + threadIdx.x;
    float x = p[i];
    const float c = 0.7978845608028654f;
    float t = tanhf(c * (x + 0.044715f * x * x * x));
    p[i] = 0.5f * x * (1.f + t);
}

// ---------------- gated scatter-add ----------------
__global__ void scatter_kernel(float* __restrict__ out) {
    int row = blockIdx.x;
    int b = row / KC;
    int idx = g_sel[row];
    float g = g_gate[row];
    float4* dst = (float4*)(out + ((size_t)b * TT + idx) * DD);
    const float4* src = (const float4*)(g_h + (size_t)row * DD);
    for (int i = threadIdx.x; i < DD / 4; i += blockDim.x) {
        float4 d = dst[i], s = src[i];
        d.x += g * s.x; d.y += g * s.y; d.z += g * s.z; d.w += g * s.w;
        dst[i] = d;
    }
}

// ---------------- host launcher ----------------
extern "C" void kernel_launch(void* const* d_in, const int* in_sizes, int n_in,
                              void* d_out, int out_size) {
    const float* x        = (const float*)d_in[0];
    const float* router_w = (const float*)d_in[1];
    const float* router_b = (const float*)d_in[2];
    const float* ln1_w    = (const float*)d_in[3];
    const float* ln1_b    = (const float*)d_in[4];
    const float* wqkv     = (const float*)d_in[5];
    const float* wo       = (const float*)d_in[6];
    const float* ln2_w    = (const float*)d_in[7];
    const float* ln2_b    = (const float*)d_in[8];
    const float* w1       = (const float*)d_in[9];
    const float* w2       = (const float*)d_in[10];
    float* out = (float*)d_out;

    float *p_h, *p_y, *p_qkv, *p_ff, *p_scores;
    cudaGetSymbolAddress((void**)&p_h, g_h);
    cudaGetSymbolAddress((void**)&p_y, g_y);
    cudaGetSymbolAddress((void**)&p_qkv, g_qkv);
    cudaGetSymbolAddress((void**)&p_ff, g_ff);
    cudaGetSymbolAddress((void**)&p_scores, g_scores);

    router_kernel<<<BB * TT, 256>>>(x, router_w, router_b);
    topk_kernel<<<BB, 1024>>>();
    gather_kernel<<<MR, 256>>>(x);

    const long long qkvB = (long long)KC * 3 * DD;

    for (int l = 0; l < LL; l++) {
        // --- attention sub-block ---
        ln_kernel<<<MR, 256>>>(p_h, ln1_w + l * DD, ln1_b + l * DD, p_y);

        // qkv = y @ Wqkv
        tc_gemm<false><<<dim3(3 * DD / 128, MR / 128, 1), 256>>>(
            p_y, wqkv + (size_t)l * DD * 3 * DD, p_qkv, p_qkv,
            MR, 3 * DD, DD, DD, 3 * DD, 3 * DD,
            1, 0, 0, 0, 0, 0, 0, 1.f, 0);

        // S = Q @ K^T / 8, batched over (b,h)
        tc_gemm<true><<<dim3(KC / 128, KC / 128, BB * HH), 256>>>(
            p_qkv /*Q*/, p_qkv + DD /*K*/, p_scores, p_scores,
            KC, KC, DHH, 3 * DD, 3 * DD, KC,
            HH, qkvB, DHH, qkvB, DHH,
            (long long)HH * KC * KC, (long long)KC * KC, 0.125f, 0);

        softmax_kernel<<<BB * HH * KC, 256>>>();

        // O = P @ V  (N = 64 per head), head-sliced into p_y
        tc_gemm<false><<<dim3(1, KC / 128, BB * HH), 256>>>(
            p_scores, p_qkv + 2 * DD /*V*/, p_y, p_y,
            KC, DHH, KC, KC, 3 * DD, DD,
            HH, (long long)HH * KC * KC, (long long)KC * KC,
            qkvB, DHH,
            (long long)KC * DD, DHH, 1.f, 0);

        // h += O @ Wo
        tc_gemm<false><<<dim3(DD / 128, MR / 128, 1), 256>>>(
            p_y, wo + (size_t)l * DD * DD, p_h, p_h,
            MR, DD, DD, DD, DD, DD,
            1, 0, 0, 0, 0, 0, 0, 1.f, 1);

        // --- MLP sub-block ---
        ln_kernel<<<MR, 256>>>(p_h, ln2_w + l * DD, ln2_b + l * DD, p_y);

        tc_gemm<false><<<dim3(FF / 128, MR / 128, 1), 256>>>(
            p_y, w1 + (size_t)l * DD * FF, p_ff, p_ff,
            MR, FF, DD, DD, FF, FF,
            1, 0, 0, 0, 0, 0, 0, 1.f, 0);

        gelu_kernel<<<(unsigned)(((size_t)MR * FF) / 256), 256>>>(p_ff);

        tc_gemm<false><<<dim3(DD / 128, MR / 128, 1), 256>>>(
            p_ff, w2 + (size_t)l * FF * DD, p_h, p_h,
            MR, DD, FF, FF, DD, DD,
            1, 0, 0, 0, 0, 0, 0, 1.f, 1);
    }

    cudaMemcpyAsync(out, x, (size_t)BB * TT * DD * sizeof(float),
                    cudaMemcpyDeviceToDevice, 0);
    scatter_kernel<<<MR, 256>>>(out);
}

// round 6
// speedup vs baseline: 5.0000x; 1.9651x over previous
#include <cuda_runtime.h>
#include <cuda_fp16.h>
#include <cstdint>
#include <math.h>

// ---------------- problem constants ----------------
#define BB 2
#define TT 4096
#define DD 1024
#define HH 16
#define DHH 64
#define FF 4096
#define KC 2048
#define LL 2
#define MR (BB * KC)   // 4096 active rows total

// ---------------- device scratch (static, allowed) ----------------
__device__ float  g_logits[BB * TT];
__device__ int    g_sel[BB * KC];
__device__ float  g_gate[BB * KC];
__device__ float  g_h[MR * DD];                       // fp32 residual stream
__device__ __half g_y[MR * DD];                       // LN output / attn out (fp16)
__device__ __half g_qkv[MR * 3 * DD];                 // fp16
__device__ __half g_ff[(size_t)MR * FF];              // fp16
__device__ __half g_scores[(size_t)BB * HH * KC * KC];// 268 MB fp16
// transposed fp16 weights ([N][K] row-major) + transposed V (padded to 128 rows/head)
__device__ __half g_wqkvt[LL * 3 * DD * DD];
__device__ __half g_w1t[(size_t)LL * FF * DD];
__device__ __half g_w2t[(size_t)LL * DD * FF];
__device__ __half g_wot[LL * DD * DD];
__device__ __half g_vt[(size_t)BB * HH * 128 * KC];

// ---------------- router logits ----------------
__global__ void router_kernel(const float* __restrict__ x,
                              const float* __restrict__ w,
                              const float* __restrict__ b) {
    int token = blockIdx.x;
    const float* xr = x + (size_t)token * DD;
    float s = 0.f;
    for (int i = threadIdx.x; i < DD; i += blockDim.x) s += xr[i] * w[i];
    __shared__ float red[8];
    for (int o = 16; o > 0; o >>= 1) s += __shfl_down_sync(0xffffffffu, s, o);
    if ((threadIdx.x & 31) == 0) red[threadIdx.x >> 5] = s;
    __syncthreads();
    if (threadIdx.x < 32) {
        float v = (threadIdx.x < 8) ? red[threadIdx.x] : 0.f;
        for (int o = 4; o > 0; o >>= 1) v += __shfl_down_sync(0xffffffffu, v, o);
        if (threadIdx.x == 0) g_logits[token] = v + b[0];
    }
}

// ---------------- top-K via in-shared bitonic sort ----------------
__device__ __forceinline__ unsigned int ford(float f) {
    unsigned int u = __float_as_uint(f);
    return (u & 0x80000000u) ? ~u : (u | 0x80000000u);
}

__global__ void topk_kernel() {
    __shared__ unsigned long long s[TT];
    int b = blockIdx.x;
    const float* lg = g_logits + b * TT;
    for (int i = threadIdx.x; i < TT; i += blockDim.x) {
        unsigned long long key = ((unsigned long long)ford(lg[i]) << 32) | (unsigned int)i;
        s[i] = key;
    }
    __syncthreads();
    for (int k = 2; k <= TT; k <<= 1) {
        for (int j = k >> 1; j > 0; j >>= 1) {
            for (int i = threadIdx.x; i < TT; i += blockDim.x) {
                int ixj = i ^ j;
                if (ixj > i) {
                    bool up = ((i & k) == 0);
                    unsigned long long a = s[i], c = s[ixj];
                    if ((a > c) == up) { s[i] = c; s[ixj] = a; }
                }
            }
            __syncthreads();
        }
    }
    for (int r = threadIdx.x; r < KC; r += blockDim.x) {
        unsigned long long key = s[TT - 1 - r];
        int idx = (int)(key & 0xffffffffu);
        g_sel[b * KC + r] = idx;
        float v = lg[idx];
        g_gate[b * KC + r] = 1.f / (1.f + expf(-v));
    }
}

// ---------------- gather active tokens ----------------
__global__ void gather_kernel(const float* __restrict__ x) {
    int row = blockIdx.x;
    int b = row / KC;
    int idx = g_sel[row];
    const float4* src = (const float4*)(x + ((size_t)b * TT + idx) * DD);
    float4* dst = (float4*)(g_h + (size_t)row * DD);
    for (int i = threadIdx.x; i < DD / 4; i += blockDim.x) dst[i] = src[i];
}

// ---------------- layernorm (fp32 in, fp16 out) ----------------
__global__ void ln_kernel(const float* __restrict__ inp,
                          const float* __restrict__ w,
                          const float* __restrict__ bia,
                          __half* __restrict__ out) {
    int row = blockIdx.x;
    const float* xr = inp + (size_t)row * DD;
    float vals[4];
    float s = 0.f, s2 = 0.f;
#pragma unroll
    for (int i = 0; i < 4; i++) {
        float v = xr[threadIdx.x + i * 256];
        vals[i] = v; s += v; s2 += v * v;
    }
    __shared__ float rs[8], rs2[8];
    for (int o = 16; o > 0; o >>= 1) {
        s  += __shfl_down_sync(0xffffffffu, s, o);
        s2 += __shfl_down_sync(0xffffffffu, s2, o);
    }
    if ((threadIdx.x & 31) == 0) { rs[threadIdx.x >> 5] = s; rs2[threadIdx.x >> 5] = s2; }
    __syncthreads();
    __shared__ float mu_s, rstd_s;
    if (threadIdx.x == 0) {
        float a = 0.f, c = 0.f;
        for (int i = 0; i < 8; i++) { a += rs[i]; c += rs2[i]; }
        float mu = a / DD;
        float var = c / DD - mu * mu;
        mu_s = mu; rstd_s = rsqrtf(var + 1e-5f);
    }
    __syncthreads();
    float mu = mu_s, rstd = rstd_s;
#pragma unroll
    for (int i = 0; i < 4; i++) {
        int c = threadIdx.x + i * 256;
        out[(size_t)row * DD + c] = __float2half((vals[i] - mu) * rstd * w[c] + bia[c]);
    }
}

// ---------------- weight transpose fp32 -> fp16 : dst[C][R] = src[R][C] ----------------
__global__ void transpose_w(const float* __restrict__ src, __half* __restrict__ dst,
                            int R, int C, long long sS, long long sD) {
    __shared__ float t[32][33];
    int z = blockIdx.z;
    src += (long long)z * sS;
    dst += (long long)z * sD;
    int rb = blockIdx.y * 32, cb = blockIdx.x * 32;
    int tx = threadIdx.x, ty = threadIdx.y;   // (32, 8)
#pragma unroll
    for (int i = 0; i < 4; i++)
        t[ty + i * 8][tx] = src[(long long)(rb + ty + i * 8) * C + cb + tx];
    __syncthreads();
#pragma unroll
    for (int i = 0; i < 4; i++)
        dst[(long long)(cb + ty + i * 8) * R + rb + tx] = __float2half(t[tx][ty + i * 8]);
}

// ---------------- V transpose fp16 -> fp16, per (b,h): [KC][64] -> [64][KC] ----------------
__global__ void transpose_v(const __half* __restrict__ qkv, __half* __restrict__ vt) {
    __shared__ __half t[32][33];
    int z = blockIdx.z;                       // b*HH + h
    int b = z / HH, h = z % HH;
    const __half* src = qkv + (long long)b * KC * 3 * DD + h * DHH + 2 * DD;
    __half* dst = vt + ((long long)b * HH + h) * 128 * KC;
    int rb = blockIdx.y * 32, cb = blockIdx.x * 32;   // rb: KC rows, cb: 64 cols
    int tx = threadIdx.x, ty = threadIdx.y;
#pragma unroll
    for (int i = 0; i < 4; i++)
        t[ty + i * 8][tx] = src[(long long)(rb + ty + i * 8) * (3 * DD) + cb + tx];
    __syncthreads();
#pragma unroll
    for (int i = 0; i < 4; i++)
        dst[(long long)(cb + ty + i * 8) * KC + rb + tx] = t[tx][ty + i * 8];
}

// ============================================================================
// FP16 tensor-core GEMM (NT): C = alpha*(A @ B^T) [+Cin] [gelu]
// A [M,Kd] fp16 row-major lda, B [N,Kd] fp16 row-major ldb.
// CTA tile 128 x TILEN, K-tile 32, 256 threads.
// TILEN=128: 2x4 warps, warp 64x32. TILEN=64: 4x2 warps, warp 32x32.
// mma.sync.aligned.m16n8k16.row.col.f32.f16.f16.f32
// ============================================================================

__device__ __forceinline__ void ldsm4(unsigned* r, unsigned addr) {
    asm volatile("ldmatrix.sync.aligned.m8n8.x4.shared.b16 {%0,%1,%2,%3}, [%4];"
                 : "=r"(r[0]), "=r"(r[1]), "=r"(r[2]), "=r"(r[3]) : "r"(addr));
}
__device__ __forceinline__ void mma_f16(float* c, const unsigned* a, const unsigned* b) {
    asm volatile(
        "mma.sync.aligned.m16n8k16.row.col.f32.f16.f16.f32 "
        "{%0,%1,%2,%3}, {%4,%5,%6,%7}, {%8,%9}, {%0,%1,%2,%3};"
        : "+f"(c[0]), "+f"(c[1]), "+f"(c[2]), "+f"(c[3])
        : "r"(a[0]), "r"(a[1]), "r"(a[2]), "r"(a[3]), "r"(b[0]), "r"(b[1]));
}
__device__ __forceinline__ float gelu_f(float x) {
    const float c = 0.7978845608028654f;
    float t = tanhf(c * (x + 0.044715f * x * x * x));
    return 0.5f * x * (1.f + t);
}

template<int TILEN>
__global__ void __launch_bounds__(256) h_gemm(
    const __half* __restrict__ A, const __half* __restrict__ B,
    const float* __restrict__ Cin, void* __restrict__ CoutV,
    int Kd, int lda, int ldb, int ldc,
    int zdiv, long long sA1, long long sA2, long long sB1, long long sB2,
    long long sC1, long long sC2, float alpha, int addC, int doGelu, int outHalf)
{
    constexpr int PA = 40;                 // smem pitch in halves (80B, ldsm conflict-free)
    constexpr int MT = (TILEN == 128) ? 4 : 2;   // m16 frags per warp
    __shared__ __half As[128 * PA];
    __shared__ __half Bs[TILEN * PA];

    int zb = blockIdx.z / zdiv, zh = blockIdx.z % zdiv;
    A += (long long)zb * sA1 + (long long)zh * sA2;
    B += (long long)zb * sB1 + (long long)zh * sB2;
    long long coff = (long long)zb * sC1 + (long long)zh * sC2;
    const float* CinP = Cin + coff;
    float*  CF = (float*)CoutV + coff;
    __half* CH = (__half*)CoutV + coff;

    int bm = blockIdx.y * 128;
    int bn = blockIdx.x * TILEN;

    int tid = threadIdx.x;
    int lane = tid & 31;
    int warp = tid >> 5;
    int warpM, warpN;
    if (TILEN == 128) { warpM = (warp >> 2) * 64; warpN = (warp & 3) * 32; }
    else              { warpM = (warp >> 1) * 32; warpN = (warp & 1) * 32; }

    // staging mapping: 16B chunks (8 halves), 4 chunks per row of 32 halves
    int qA = tid & 3;            // k-chunk
    int rA = tid >> 2;           // 0..63 (+64 second pass)

    // ldmatrix addresses
    unsigned aBase = (unsigned)__cvta_generic_to_shared(As);
    unsigned bBase = (unsigned)__cvta_generic_to_shared(Bs);
    unsigned addrA[MT];
#pragma unroll
    for (int mt = 0; mt < MT; mt++)
        addrA[mt] = aBase + (unsigned)(((warpM + mt * 16 + (lane & 15)) * PA + (lane >> 4) * 8) * 2);
    unsigned addrB[2];
#pragma unroll
    for (int np = 0; np < 2; np++)
        addrB[np] = bBase + (unsigned)(((warpN + np * 16 + (lane & 7) + ((lane >> 4) & 1) * 8) * PA
                                        + ((lane >> 3) & 1) * 8) * 2);

    float acc[MT][4][4];
#pragma unroll
    for (int i = 0; i < MT; i++)
#pragma unroll
        for (int j = 0; j < 4; j++)
#pragma unroll
            for (int q = 0; q < 4; q++) acc[i][j][q] = 0.f;

    uint4 ra[2], rb[2];
    const int BPASS = TILEN / 64;   // B staging passes (chunks of 256)

    // ---- prologue: tile 0 ----
#pragma unroll
    for (int t = 0; t < 2; t++)
        ra[t] = *(const uint4*)(A + (long long)(bm + rA + t * 64) * lda + qA * 8);
#pragma unroll
    for (int t = 0; t < BPASS; t++)
        rb[t] = *(const uint4*)(B + (long long)(bn + rA + t * 64) * ldb + qA * 8);
#pragma unroll
    for (int t = 0; t < 2; t++)
        *(uint4*)&As[(rA + t * 64) * PA + qA * 8] = ra[t];
#pragma unroll
    for (int t = 0; t < BPASS; t++)
        *(uint4*)&Bs[(rA + t * 64) * PA + qA * 8] = rb[t];
    __syncthreads();

    int KT = Kd >> 5;
    for (int kt = 0; kt < KT; kt++) {
        bool next = (kt + 1 < KT);
        if (next) {
            int k0 = (kt + 1) * 32;
#pragma unroll
            for (int t = 0; t < 2; t++)
                ra[t] = *(const uint4*)(A + (long long)(bm + rA + t * 64) * lda + k0 + qA * 8);
#pragma unroll
            for (int t = 0; t < BPASS; t++)
                rb[t] = *(const uint4*)(B + (long long)(bn + rA + t * 64) * ldb + k0 + qA * 8);
        }

#pragma unroll
        for (int k16 = 0; k16 < 2; k16++) {
            unsigned aF[MT][4];
#pragma unroll
            for (int mt = 0; mt < MT; mt++)
                ldsm4(aF[mt], addrA[mt] + k16 * 32);
            unsigned bF[2][4];
#pragma unroll
            for (int np = 0; np < 2; np++)
                ldsm4(bF[np], addrB[np] + k16 * 32);
#pragma unroll
            for (int mt = 0; mt < MT; mt++)
#pragma unroll
                for (int np = 0; np < 2; np++) {
                    mma_f16(acc[mt][np * 2 + 0], aF[mt], &bF[np][0]);
                    mma_f16(acc[mt][np * 2 + 1], aF[mt], &bF[np][2]);
                }
        }

        if (next) {
            __syncthreads();
#pragma unroll
            for (int t = 0; t < 2; t++)
                *(uint4*)&As[(rA + t * 64) * PA + qA * 8] = ra[t];
#pragma unroll
            for (int t = 0; t < BPASS; t++)
                *(uint4*)&Bs[(rA + t * 64) * PA + qA * 8] = rb[t];
            __syncthreads();
        }
    }

    // ---- epilogue ----
    int grp = lane >> 2, c2 = (lane & 3) * 2;
#pragma unroll
    for (int mt = 0; mt < MT; mt++) {
#pragma unroll
        for (int j = 0; j < 4; j++) {
            int col = bn + warpN + (j >> 1) * 16 + (j & 1) * 8 + c2;
            long long r0 = (long long)(bm + warpM + mt * 16 + grp) * ldc + col;
            long long r1 = r0 + 8LL * ldc;
            float v00 = acc[mt][j][0] * alpha, v01 = acc[mt][j][1] * alpha;
            float v10 = acc[mt][j][2] * alpha, v11 = acc[mt][j][3] * alpha;
            if (doGelu) {
                v00 = gelu_f(v00); v01 = gelu_f(v01);
                v10 = gelu_f(v10); v11 = gelu_f(v11);
            }
            if (addC) {
                float2 ci0 = *(const float2*)(CinP + r0);
                float2 ci1 = *(const float2*)(CinP + r1);
                v00 += ci0.x; v01 += ci0.y;
                v10 += ci1.x; v11 += ci1.y;
            }
            if (outHalf) {
                *(__half2*)(CH + r0) = __halves2half2(__float2half(v00), __float2half(v01));
                *(__half2*)(CH + r1) = __halves2half2(__float2half(v10), __float2half(v11));
            } else {
                *(float2*)(CF + r0) = make_float2(v00, v01);
                *(float2*)(CF + r1) = make_float2(v10, v11);
            }
        }
    }
}

// ---------------- row softmax over fp16 scores rows of length KC ----------------
__global__ void softmax_kernel() {
    size_t row = blockIdx.x;
    __half* p = g_scores + row * KC;
    int tid = threadIdx.x;
    float vals[8];
    float mx = -1e30f;
#pragma unroll
    for (int i = 0; i < 8; i++) {
        float v = __half2float(p[tid + i * 256]);
        vals[i] = v; mx = fmaxf(mx, v);
    }
    __shared__ float red[8];
    for (int o = 16; o > 0; o >>= 1) mx = fmaxf(mx, __shfl_xor_sync(0xffffffffu, mx, o));
    if ((tid & 31) == 0) red[tid >> 5] = mx;
    __syncthreads();
    __shared__ float m_s, s_s;
    if (tid == 0) {
        float m = red[0];
        for (int i = 1; i < 8; i++) m = fmaxf(m, red[i]);
        m_s = m;
    }
    __syncthreads();
    mx = m_s;
    float s = 0.f;
#pragma unroll
    for (int i = 0; i < 8; i++) { vals[i] = expf(vals[i] - mx); s += vals[i]; }
    for (int o = 16; o > 0; o >>= 1) s += __shfl_down_sync(0xffffffffu, s, o);
    if ((tid & 31) == 0) red[tid >> 5] = s;
    __syncthreads();
    if (tid == 0) {
        float a = 0.f;
        for (int i = 0; i < 8; i++) a += red[i];
        s_s = a;
    }
    __syncthreads();
    float inv = 1.f / s_s;
#pragma unroll
    for (int i = 0; i < 8; i++) p[tid + i * 256] = __float2half(vals[i] * inv);
}

// ---------------- gated scatter-add ----------------
__global__ void scatter_kernel(float* __restrict__ out) {
    int row = blockIdx.x;
    int b = row / KC;
    int idx = g_sel[row];
    float g = g_gate[row];
    float4* dst = (float4*)(out + ((size_t)b * TT + idx) * DD);
    const float4* src = (const float4*)(g_h + (size_t)row * DD);
    for (int i = threadIdx.x; i < DD / 4; i += blockDim.x) {
        float4 d = dst[i], s = src[i];
        d.x += g * s.x; d.y += g * s.y; d.z += g * s.z; d.w += g * s.w;
        dst[i] = d;
    }
}

// ---------------- host launcher ----------------
extern "C" void kernel_launch(void* const* d_in, const int* in_sizes, int n_in,
                              void* d_out, int out_size) {
    const float* x        = (const float*)d_in[0];
    const float* router_w = (const float*)d_in[1];
    const float* router_b = (const float*)d_in[2];
    const float* ln1_w    = (const float*)d_in[3];
    const float* ln1_b    = (const float*)d_in[4];
    const float* wqkv     = (const float*)d_in[5];
    const float* wo       = (const float*)d_in[6];
    const float* ln2_w    = (const float*)d_in[7];
    const float* ln2_b    = (const float*)d_in[8];
    const float* w1       = (const float*)d_in[9];
    const float* w2       = (const float*)d_in[10];
    float* out = (float*)d_out;

    float *p_h;
    __half *p_y, *p_qkv, *p_ff, *p_scores;
    __half *p_wqkvt, *p_w1t, *p_w2t, *p_wot, *p_vt;
    cudaGetSymbolAddress((void**)&p_h, g_h);
    cudaGetSymbolAddress((void**)&p_y, g_y);
    cudaGetSymbolAddress((void**)&p_qkv, g_qkv);
    cudaGetSymbolAddress((void**)&p_ff, g_ff);
    cudaGetSymbolAddress((void**)&p_scores, g_scores);
    cudaGetSymbolAddress((void**)&p_wqkvt, g_wqkvt);
    cudaGetSymbolAddress((void**)&p_w1t, g_w1t);
    cudaGetSymbolAddress((void**)&p_w2t, g_w2t);
    cudaGetSymbolAddress((void**)&p_wot, g_wot);
    cudaGetSymbolAddress((void**)&p_vt, g_vt);

    router_kernel<<<BB * TT, 256>>>(x, router_w, router_b);
    topk_kernel<<<BB, 1024>>>();
    gather_kernel<<<MR, 256>>>(x);

    // pre-transpose + fp16-convert weights: W[K,N] -> Wt[N,K]
    dim3 tb(32, 8);
    transpose_w<<<dim3(3 * DD / 32, DD / 32, LL), tb>>>(
        wqkv, p_wqkvt, DD, 3 * DD, (long long)DD * 3 * DD, (long long)3 * DD * DD);
    transpose_w<<<dim3(FF / 32, DD / 32, LL), tb>>>(
        w1, p_w1t, DD, FF, (long long)DD * FF, (long long)FF * DD);
    transpose_w<<<dim3(DD / 32, FF / 32, LL), tb>>>(
        w2, p_w2t, FF, DD, (long long)FF * DD, (long long)DD * FF);
    transpose_w<<<dim3(DD / 32, DD / 32, LL), tb>>>(
        wo, p_wot, DD, DD, (long long)DD * DD, (long long)DD * DD);

    const long long qkvB = (long long)KC * 3 * DD;   // per-batch stride in qkv
    const long long scH  = (long long)KC * KC;       // per-head stride in scores
    const long long scB  = (long long)HH * scH;
    const long long vtH  = (long long)128 * KC;      // per-head Vt slot (padded)
    const long long vtB  = (long long)HH * vtH;

    for (int l = 0; l < LL; l++) {
        // --- attention sub-block ---
        ln_kernel<<<MR, 256>>>(p_h, ln1_w + l * DD, ln1_b + l * DD, p_y);

        // qkv = y @ Wqkv^T  (fp16 out)
        h_gemm<128><<<dim3(3 * DD / 128, MR / 128, 1), 256>>>(
            p_y, p_wqkvt + (size_t)l * 3 * DD * DD, p_h, p_qkv,
            DD, DD, DD, 3 * DD,
            1, 0, 0, 0, 0, 0, 0, 1.f, 0, 0, 1);

        // S = Q @ K^T / 8, batched over (b,h), fp16 out
        h_gemm<128><<<dim3(KC / 128, KC / 128, BB * HH), 256>>>(
            p_qkv /*Q*/, p_qkv + DD /*K*/, p_h, p_scores,
            DHH, 3 * DD, 3 * DD, KC,
            HH, qkvB, DHH, qkvB, DHH, scB, scH, 0.125f, 0, 0, 1);

        softmax_kernel<<<BB * HH * KC, 256>>>();

        // V[KC,64] -> Vt[64,KC] per (b,h)
        transpose_v<<<dim3(DHH / 32, KC / 32, BB * HH), tb>>>(p_qkv, p_vt);

        // O = P @ V (N=64 tile, no waste), head-sliced into y (fp16)
        h_gemm<64><<<dim3(1, KC / 128, BB * HH), 256>>>(
            p_scores, p_vt, p_h, p_y,
            KC, KC, KC, DD,
            HH, scB, scH, vtB, vtH,
            (long long)KC * DD, DHH, 1.f, 0, 0, 1);

        // h += O @ Wo^T (fp32 out + residual)
        h_gemm<128><<<dim3(DD / 128, MR / 128, 1), 256>>>(
            p_y, p_wot + (size_t)l * DD * DD, p_h, p_h,
            DD, DD, DD, DD,
            1, 0, 0, 0, 0, 0, 0, 1.f, 1, 0, 0);

        // --- MLP sub-block ---
        ln_kernel<<<MR, 256>>>(p_h, ln2_w + l * DD, ln2_b + l * DD, p_y);

        // ff = gelu(y @ W1^T)  (fp16 out, gelu fused)
        h_gemm<128><<<dim3(FF / 128, MR / 128, 1), 256>>>(
            p_y, p_w1t + (size_t)l * FF * DD, p_h, p_ff,
            DD, DD, DD, FF,
            1, 0, 0, 0, 0, 0, 0, 1.f, 0, 1, 1);

        // h += ff @ W2^T (fp32 out + residual)
        h_gemm<128><<<dim3(DD / 128, MR / 128, 1), 256>>>(
            p_ff, p_w2t + (size_t)l * DD * FF, p_h, p_h,
            FF, FF, FF, DD,
            1, 0, 0, 0, 0, 0, 0, 1.f, 1, 0, 0);
    }

    cudaMemcpyAsync(out, x, (size_t)BB * TT * DD * sizeof(float),
                    cudaMemcpyDeviceToDevice, 0);
    scatter_kernel<<<MR, 256>>>(out);
}

// round 12
// speedup vs baseline: 6.9907x; 1.3981x over previous
#include <cuda_runtime.h>
#include <cuda_fp16.h>
#include <cstdint>
#include <math.h>

// ---------------- problem constants ----------------
#define BB 2
#define TT 4096
#define DD 1024
#define HH 16
#define DHH 64
#define FF 4096
#define KC 2048
#define LL 2
#define MR (BB * KC)   // 4096 active rows total

// ---------------- device scratch (static, allowed) ----------------
__device__ float  g_logits[BB * TT];
__device__ int    g_sel[BB * KC];
__device__ float  g_gate[BB * KC];
__device__ float  g_h[MR * DD];                       // fp32 residual stream
__device__ __half g_y[MR * DD];                       // LN output / attn out (fp16)
__device__ __half g_qkv[MR * 3 * DD];                 // fp16
__device__ __half g_ff[(size_t)MR * FF];              // fp16
// transposed fp16 weights ([N][K] row-major)
__device__ __half g_wqkvt[LL * 3 * DD * DD];
__device__ __half g_w1t[(size_t)LL * FF * DD];
__device__ __half g_w2t[(size_t)LL * DD * FF];
__device__ __half g_wot[LL * DD * DD];

// ---------------- router logits ----------------
__global__ void router_kernel(const float* __restrict__ x,
                              const float* __restrict__ w,
                              const float* __restrict__ b) {
    int token = blockIdx.x;
    const float* xr = x + (size_t)token * DD;
    float s = 0.f;
    for (int i = threadIdx.x; i < DD; i += blockDim.x) s += xr[i] * w[i];
    __shared__ float red[8];
    for (int o = 16; o > 0; o >>= 1) s += __shfl_down_sync(0xffffffffu, s, o);
    if ((threadIdx.x & 31) == 0) red[threadIdx.x >> 5] = s;
    __syncthreads();
    if (threadIdx.x < 32) {
        float v = (threadIdx.x < 8) ? red[threadIdx.x] : 0.f;
        for (int o = 4; o > 0; o >>= 1) v += __shfl_down_sync(0xffffffffu, v, o);
        if (threadIdx.x == 0) g_logits[token] = v + b[0];
    }
}

// ---------------- top-K via in-shared bitonic sort ----------------
__device__ __forceinline__ unsigned int ford(float f) {
    unsigned int u = __float_as_uint(f);
    return (u & 0x80000000u) ? ~u : (u | 0x80000000u);
}

__global__ void topk_kernel() {
    __shared__ unsigned long long s[TT];
    int b = blockIdx.x;
    const float* lg = g_logits + b * TT;
    for (int i = threadIdx.x; i < TT; i += blockDim.x) {
        unsigned long long key = ((unsigned long long)ford(lg[i]) << 32) | (unsigned int)i;
        s[i] = key;
    }
    __syncthreads();
    for (int k = 2; k <= TT; k <<= 1) {
        for (int j = k >> 1; j > 0; j >>= 1) {
            for (int i = threadIdx.x; i < TT; i += blockDim.x) {
                int ixj = i ^ j;
                if (ixj > i) {
                    bool up = ((i & k) == 0);
                    unsigned long long a = s[i], c = s[ixj];
                    if ((a > c) == up) { s[i] = c; s[ixj] = a; }
                }
            }
            __syncthreads();
        }
    }
    for (int r = threadIdx.x; r < KC; r += blockDim.x) {
        unsigned long long key = s[TT - 1 - r];
        int idx = (int)(key & 0xffffffffu);
        g_sel[b * KC + r] = idx;
        float v = lg[idx];
        g_gate[b * KC + r] = 1.f / (1.f + expf(-v));
    }
}

// ---------------- gather active tokens ----------------
__global__ void gather_kernel(const float* __restrict__ x) {
    int row = blockIdx.x;
    int b = row / KC;
    int idx = g_sel[row];
    const float4* src = (const float4*)(x + ((size_t)b * TT + idx) * DD);
    float4* dst = (float4*)(g_h + (size_t)row * DD);
    for (int i = threadIdx.x; i < DD / 4; i += blockDim.x) dst[i] = src[i];
}

// ---------------- layernorm (fp32 in, fp16 out) ----------------
__global__ void ln_kernel(const float* __restrict__ inp,
                          const float* __restrict__ w,
                          const float* __restrict__ bia,
                          __half* __restrict__ out) {
    int row = blockIdx.x;
    const float* xr = inp + (size_t)row * DD;
    float vals[4];
    float s = 0.f, s2 = 0.f;
#pragma unroll
    for (int i = 0; i < 4; i++) {
        float v = xr[threadIdx.x + i * 256];
        vals[i] = v; s += v; s2 += v * v;
    }
    __shared__ float rs[8], rs2[8];
    for (int o = 16; o > 0; o >>= 1) {
        s  += __shfl_down_sync(0xffffffffu, s, o);
        s2 += __shfl_down_sync(0xffffffffu, s2, o);
    }
    if ((threadIdx.x & 31) == 0) { rs[threadIdx.x >> 5] = s; rs2[threadIdx.x >> 5] = s2; }
    __syncthreads();
    __shared__ float mu_s, rstd_s;
    if (threadIdx.x == 0) {
        float a = 0.f, c = 0.f;
        for (int i = 0; i < 8; i++) { a += rs[i]; c += rs2[i]; }
        float mu = a / DD;
        float var = c / DD - mu * mu;
        mu_s = mu; rstd_s = rsqrtf(var + 1e-5f);
    }
    __syncthreads();
    float mu = mu_s, rstd = rstd_s;
#pragma unroll
    for (int i = 0; i < 4; i++) {
        int c = threadIdx.x + i * 256;
        out[(size_t)row * DD + c] = __float2half((vals[i] - mu) * rstd * w[c] + bia[c]);
    }
}

// ---------------- weight transpose fp32 -> fp16 : dst[C][R] = src[R][C] ----------------
__global__ void transpose_w(const float* __restrict__ src, __half* __restrict__ dst,
                            int R, int C, long long sS, long long sD) {
    __shared__ float t[32][33];
    int z = blockIdx.z;
    src += (long long)z * sS;
    dst += (long long)z * sD;
    int rb = blockIdx.y * 32, cb = blockIdx.x * 32;
    int tx = threadIdx.x, ty = threadIdx.y;   // (32, 8)
#pragma unroll
    for (int i = 0; i < 4; i++)
        t[ty + i * 8][tx] = src[(long long)(rb + ty + i * 8) * C + cb + tx];
    __syncthreads();
#pragma unroll
    for (int i = 0; i < 4; i++)
        dst[(long long)(cb + ty + i * 8) * R + rb + tx] = __float2half(t[tx][ty + i * 8]);
}

// ---------------- mma / ldmatrix helpers ----------------
__device__ __forceinline__ void ldsm4(unsigned* r, unsigned addr) {
    asm volatile("ldmatrix.sync.aligned.m8n8.x4.shared.b16 {%0,%1,%2,%3}, [%4];"
                 : "=r"(r[0]), "=r"(r[1]), "=r"(r[2]), "=r"(r[3]) : "r"(addr));
}
__device__ __forceinline__ void ldsm4t(unsigned* r, unsigned addr) {
    asm volatile("ldmatrix.sync.aligned.m8n8.x4.trans.shared.b16 {%0,%1,%2,%3}, [%4];"
                 : "=r"(r[0]), "=r"(r[1]), "=r"(r[2]), "=r"(r[3]) : "r"(addr));
}
__device__ __forceinline__ void mma_f16(float* c, const unsigned* a, const unsigned* b) {
    asm volatile(
        "mma.sync.aligned.m16n8k16.row.col.f32.f16.f16.f32 "
        "{%0,%1,%2,%3}, {%4,%5,%6,%7}, {%8,%9}, {%0,%1,%2,%3};"
        : "+f"(c[0]), "+f"(c[1]), "+f"(c[2]), "+f"(c[3])
        : "r"(a[0]), "r"(a[1]), "r"(a[2]), "r"(a[3]), "r"(b[0]), "r"(b[1]));
}
__device__ __forceinline__ void cp16(uint32_t dst, const void* src) {
    asm volatile("cp.async.cg.shared.global [%0], [%1], 16;\n" :: "r"(dst), "l"(src));
}
__device__ __forceinline__ float gelu_f(float x) {
    const float c = 0.7978845608028654f;
    float t = tanhf(c * (x + 0.044715f * x * x * x));
    return 0.5f * x * (1.f + t);
}
__device__ __forceinline__ unsigned pack_h2(float a, float b) {
    __half2 h = __halves2half2(__float2half(a), __float2half(b));
    return *(unsigned*)&h;
}

// ============================================================================
// FP16 tensor-core GEMM (NT): C = alpha*(A @ B^T) [+Cin] [gelu]
// A [M,Kd] fp16 row-major lda, B [N,Kd] fp16 row-major ldb.
// CTA tile 128 x 128, K-tile 32, 256 threads, 2x4 warps, warp 64x32.
// ============================================================================
__global__ void __launch_bounds__(256) h_gemm(
    const __half* __restrict__ A, const __half* __restrict__ B,
    const float* __restrict__ Cin, void* __restrict__ CoutV,
    int Kd, int lda, int ldb, int ldc,
    float alpha, int addC, int doGelu, int outHalf)
{
    constexpr int PA = 40;
    __shared__ __half As[128 * PA];
    __shared__ __half Bs[128 * PA];

    const float* CinP = Cin;
    float*  CF = (float*)CoutV;
    __half* CH = (__half*)CoutV;

    int bm = blockIdx.y * 128;
    int bn = blockIdx.x * 128;

    int tid = threadIdx.x;
    int lane = tid & 31;
    int warp = tid >> 5;
    int warpM = (warp >> 2) * 64;
    int warpN = (warp & 3) * 32;

    int qA = tid & 3;
    int rA = tid >> 2;

    unsigned aBase = (unsigned)__cvta_generic_to_shared(As);
    unsigned bBase = (unsigned)__cvta_generic_to_shared(Bs);
    unsigned addrA[4];
#pragma unroll
    for (int mt = 0; mt < 4; mt++)
        addrA[mt] = aBase + (unsigned)(((warpM + mt * 16 + (lane & 15)) * PA + (lane >> 4) * 8) * 2);
    unsigned addrB[2];
#pragma unroll
    for (int np = 0; np < 2; np++)
        addrB[np] = bBase + (unsigned)(((warpN + np * 16 + (lane & 7) + ((lane >> 4) & 1) * 8) * PA
                                        + ((lane >> 3) & 1) * 8) * 2);

    float acc[4][4][4];
#pragma unroll
    for (int i = 0; i < 4; i++)
#pragma unroll
        for (int j = 0; j < 4; j++)
#pragma unroll
            for (int q = 0; q < 4; q++) acc[i][j][q] = 0.f;

    uint4 ra[2], rb[2];

#pragma unroll
    for (int t = 0; t < 2; t++)
        ra[t] = *(const uint4*)(A + (long long)(bm + rA + t * 64) * lda + qA * 8);
#pragma unroll
    for (int t = 0; t < 2; t++)
        rb[t] = *(const uint4*)(B + (long long)(bn + rA + t * 64) * ldb + qA * 8);
#pragma unroll
    for (int t = 0; t < 2; t++)
        *(uint4*)&As[(rA + t * 64) * PA + qA * 8] = ra[t];
#pragma unroll
    for (int t = 0; t < 2; t++)
        *(uint4*)&Bs[(rA + t * 64) * PA + qA * 8] = rb[t];
    __syncthreads();

    int KT = Kd >> 5;
    for (int kt = 0; kt < KT; kt++) {
        bool next = (kt + 1 < KT);
        if (next) {
            int k0 = (kt + 1) * 32;
#pragma unroll
            for (int t = 0; t < 2; t++)
                ra[t] = *(const uint4*)(A + (long long)(bm + rA + t * 64) * lda + k0 + qA * 8);
#pragma unroll
            for (int t = 0; t < 2; t++)
                rb[t] = *(const uint4*)(B + (long long)(bn + rA + t * 64) * ldb + k0 + qA * 8);
        }

#pragma unroll
        for (int k16 = 0; k16 < 2; k16++) {
            unsigned aF[4][4];
#pragma unroll
            for (int mt = 0; mt < 4; mt++)
                ldsm4(aF[mt], addrA[mt] + k16 * 32);
            unsigned bF[2][4];
#pragma unroll
            for (int np = 0; np < 2; np++)
                ldsm4(bF[np], addrB[np] + k16 * 32);
#pragma unroll
            for (int mt = 0; mt < 4; mt++)
#pragma unroll
                for (int np = 0; np < 2; np++) {
                    mma_f16(acc[mt][np * 2 + 0], aF[mt], &bF[np][0]);
                    mma_f16(acc[mt][np * 2 + 1], aF[mt], &bF[np][2]);
                }
        }

        if (next) {
            __syncthreads();
#pragma unroll
            for (int t = 0; t < 2; t++)
                *(uint4*)&As[(rA + t * 64) * PA + qA * 8] = ra[t];
#pragma unroll
            for (int t = 0; t < 2; t++)
                *(uint4*)&Bs[(rA + t * 64) * PA + qA * 8] = rb[t];
            __syncthreads();
        }
    }

    int grp = lane >> 2, c2 = (lane & 3) * 2;
#pragma unroll
    for (int mt = 0; mt < 4; mt++) {
#pragma unroll
        for (int j = 0; j < 4; j++) {
            int col = bn + warpN + (j >> 1) * 16 + (j & 1) * 8 + c2;
            long long r0 = (long long)(bm + warpM + mt * 16 + grp) * ldc + col;
            long long r1 = r0 + 8LL * ldc;
            float v00 = acc[mt][j][0] * alpha, v01 = acc[mt][j][1] * alpha;
            float v10 = acc[mt][j][2] * alpha, v11 = acc[mt][j][3] * alpha;
            if (doGelu) {
                v00 = gelu_f(v00); v01 = gelu_f(v01);
                v10 = gelu_f(v10); v11 = gelu_f(v11);
            }
            if (addC) {
                float2 ci0 = *(const float2*)(CinP + r0);
                float2 ci1 = *(const float2*)(CinP + r1);
                v00 += ci0.x; v01 += ci0.y;
                v10 += ci1.x; v11 += ci1.y;
            }
            if (outHalf) {
                *(__half2*)(CH + r0) = __halves2half2(__float2half(v00), __float2half(v01));
                *(__half2*)(CH + r1) = __halves2half2(__float2half(v10), __float2half(v11));
            } else {
                *(float2*)(CF + r0) = make_float2(v00, v01);
                *(float2*)(CF + r1) = make_float2(v10, v11);
            }
        }
    }
}

// ============================================================================
// Fused FlashAttention-2 over the active token set.
// Grid: (KC/128 q-tiles, B*H). 256 threads (8 warps x 16 q-rows).
// Q/K/V read head-sliced from g_qkv (fp16, row stride 3*DD).
// S fp32 in registers, online softmax (exp2), P->fp16 regs, V via ldmatrix.trans.
// O (fp16) written head-sliced into g_y.
// ============================================================================
#define FPITCH 72   // smem pitch in halves

__global__ void __launch_bounds__(256) flash_kernel(
    const __half* __restrict__ qkv, __half* __restrict__ yout)
{
    extern __shared__ __half fsm[];
    __half* Qs = fsm;                       // 128*FPITCH
    __half* Ks0 = fsm + 128 * FPITCH;
    __half* Ks1 = fsm + 2 * 128 * FPITCH;
    __half* Vs0 = fsm + 3 * 128 * FPITCH;
    __half* Vs1 = fsm + 4 * 128 * FPITCH;

    int bh = blockIdx.y;
    int b = bh / HH, h = bh % HH;
    const __half* Qg = qkv + (size_t)b * KC * 3 * DD + h * DHH;
    const __half* Kg = Qg + DD;
    const __half* Vg = Qg + 2 * DD;
    int q0 = blockIdx.x * 128;

    int tid = threadIdx.x;
    int lane = tid & 31, warp = tid >> 5;
    int wq = warp * 16;

    unsigned qB = (unsigned)__cvta_generic_to_shared(Qs);
    unsigned kB0 = (unsigned)__cvta_generic_to_shared(Ks0);
    unsigned kB1 = (unsigned)__cvta_generic_to_shared(Ks1);
    unsigned vB0 = (unsigned)__cvta_generic_to_shared(Vs0);
    unsigned vB1 = (unsigned)__cvta_generic_to_shared(Vs1);

    // staging: 128 rows x 8 16B-chunks (64 halves = full head dim) per matrix.
    // 1024 chunks / 256 threads = 4 per thread: rows tid>>2 and tid>>2+64,
    // chunks (tid&3)*2 and (tid&3)*2+1.
    int sr = tid >> 2;           // row 0..63 (+64 second pass)
    int sq = tid & 3;            // chunk-pair index (covers chunks sq*2, sq*2+1)

    auto load_q = [&]() {
#pragma unroll
        for (int p = 0; p < 2; p++)
#pragma unroll
            for (int c = 0; c < 2; c++)
                cp16(qB + (unsigned)(((sr + p * 64) * FPITCH + (sq * 2 + c) * 8) * 2),
                     Qg + (long long)(q0 + sr + p * 64) * (3 * DD) + (sq * 2 + c) * 8);
    };
    auto load_kv = [&](int it, unsigned kb, unsigned vb) {
#pragma unroll
        for (int p = 0; p < 2; p++) {
            int r0 = it * 128 + sr + p * 64;
#pragma unroll
            for (int c = 0; c < 2; c++)
                cp16(kb + (unsigned)(((sr + p * 64) * FPITCH + (sq * 2 + c) * 8) * 2),
                     Kg + (long long)r0 * (3 * DD) + (sq * 2 + c) * 8);
#pragma unroll
            for (int c = 0; c < 2; c++)
                cp16(vb + (unsigned)(((sr + p * 64) * FPITCH + (sq * 2 + c) * 8) * 2),
                     Vg + (long long)r0 * (3 * DD) + (sq * 2 + c) * 8);
        }
    };

    // ldmatrix lane offsets
    unsigned qAddr = qB + (unsigned)(((wq + (lane & 15)) * FPITCH + (lane >> 4) * 8) * 2);
    unsigned kLane = (unsigned)((((lane & 7) + ((lane >> 4) & 1) * 8) * FPITCH
                                 + ((lane >> 3) & 1) * 8) * 2);
    unsigned vLane = (unsigned)((((lane & 7) + ((lane >> 3) & 1) * 8) * FPITCH
                                 + (lane >> 4) * 8) * 2);

    float m0 = -1e30f, m1 = -1e30f, l0 = 0.f, l1 = 0.f;
    float O[8][4];
#pragma unroll
    for (int i = 0; i < 8; i++)
#pragma unroll
        for (int j = 0; j < 4; j++) O[i][j] = 0.f;

    const float LOG2E = 1.4426950408889634f;

    // prologue: Q + tile 0
    load_q();
    load_kv(0, kB0, vB0);
    asm volatile("cp.async.commit_group;");

    const int NIT = KC / 128;
    for (int it = 0; it < NIT; it++) {
        asm volatile("cp.async.wait_group 0;");
        __syncthreads();
        unsigned kb = (it & 1) ? kB1 : kB0;
        unsigned vb = (it & 1) ? vB1 : vB0;
        if (it + 1 < NIT) {
            load_kv(it + 1, (it & 1) ? kB0 : kB1, (it & 1) ? vB0 : vB1);
            asm volatile("cp.async.commit_group;");
        }

        // ---- S = Q K^T ----
        float S[16][4];
#pragma unroll
        for (int i = 0; i < 16; i++)
#pragma unroll
            for (int j = 0; j < 4; j++) S[i][j] = 0.f;

#pragma unroll
        for (int dhc = 0; dhc < 4; dhc++) {
            unsigned qa[4];
            ldsm4(qa, qAddr + dhc * 32);
#pragma unroll
            for (int nt = 0; nt < 8; nt++) {
                unsigned kf[4];
                ldsm4(kf, kb + kLane + (unsigned)(nt * 16 * FPITCH * 2 + dhc * 32));
                mma_f16(S[2 * nt], qa, &kf[0]);
                mma_f16(S[2 * nt + 1], qa, &kf[2]);
            }
        }

        // ---- online softmax ----
        float mx0 = -1e30f, mx1 = -1e30f;
#pragma unroll
        for (int i = 0; i < 16; i++) {
#pragma unroll
            for (int j = 0; j < 4; j++) S[i][j] *= 0.125f;
            mx0 = fmaxf(mx0, fmaxf(S[i][0], S[i][1]));
            mx1 = fmaxf(mx1, fmaxf(S[i][2], S[i][3]));
        }
        mx0 = fmaxf(mx0, __shfl_xor_sync(0xffffffffu, mx0, 1));
        mx0 = fmaxf(mx0, __shfl_xor_sync(0xffffffffu, mx0, 2));
        mx1 = fmaxf(mx1, __shfl_xor_sync(0xffffffffu, mx1, 1));
        mx1 = fmaxf(mx1, __shfl_xor_sync(0xffffffffu, mx1, 2));
        float mn0 = fmaxf(m0, mx0), mn1 = fmaxf(m1, mx1);
        float sc0 = exp2f((m0 - mn0) * LOG2E);
        float sc1 = exp2f((m1 - mn1) * LOG2E);
        float sum0 = 0.f, sum1 = 0.f;
#pragma unroll
        for (int i = 0; i < 16; i++) {
            S[i][0] = exp2f((S[i][0] - mn0) * LOG2E);
            S[i][1] = exp2f((S[i][1] - mn0) * LOG2E);
            S[i][2] = exp2f((S[i][2] - mn1) * LOG2E);
            S[i][3] = exp2f((S[i][3] - mn1) * LOG2E);
            sum0 += S[i][0] + S[i][1];
            sum1 += S[i][2] + S[i][3];
        }
        sum0 += __shfl_xor_sync(0xffffffffu, sum0, 1);
        sum0 += __shfl_xor_sync(0xffffffffu, sum0, 2);
        sum1 += __shfl_xor_sync(0xffffffffu, sum1, 1);
        sum1 += __shfl_xor_sync(0xffffffffu, sum1, 2);
        l0 = l0 * sc0 + sum0;
        l1 = l1 * sc1 + sum1;
        m0 = mn0; m1 = mn1;
#pragma unroll
        for (int dn = 0; dn < 8; dn++) {
            O[dn][0] *= sc0; O[dn][1] *= sc0;
            O[dn][2] *= sc1; O[dn][3] *= sc1;
        }

        // ---- O += P V ----
#pragma unroll
        for (int kc = 0; kc < 8; kc++) {
            unsigned pa[4];
            pa[0] = pack_h2(S[2 * kc][0], S[2 * kc][1]);
            pa[1] = pack_h2(S[2 * kc][2], S[2 * kc][3]);
            pa[2] = pack_h2(S[2 * kc + 1][0], S[2 * kc + 1][1]);
            pa[3] = pack_h2(S[2 * kc + 1][2], S[2 * kc + 1][3]);
#pragma unroll
            for (int dn = 0; dn < 4; dn++) {
                unsigned vf[4];
                ldsm4t(vf, vb + vLane + (unsigned)(kc * 16 * FPITCH * 2 + dn * 32));
                mma_f16(O[2 * dn], pa, &vf[0]);
                mma_f16(O[2 * dn + 1], pa, &vf[2]);
            }
        }
        __syncthreads();
    }

    // ---- writeout ----
    float inv0 = 1.f / l0, inv1 = 1.f / l1;
    int row0 = b * KC + q0 + wq + (lane >> 2);
    int row1 = row0 + 8;
    int colb = h * DHH + (lane & 3) * 2;
#pragma unroll
    for (int dn = 0; dn < 8; dn++) {
        int col = colb + dn * 8;
        *(__half2*)(yout + (size_t)row0 * DD + col) =
            __halves2half2(__float2half(O[dn][0] * inv0), __float2half(O[dn][1] * inv0));
        *(__half2*)(yout + (size_t)row1 * DD + col) =
            __halves2half2(__float2half(O[dn][2] * inv1), __float2half(O[dn][3] * inv1));
    }
}

// ---------------- gated scatter-add ----------------
__global__ void scatter_kernel(float* __restrict__ out) {
    int row = blockIdx.x;
    int b = row / KC;
    int idx = g_sel[row];
    float g = g_gate[row];
    float4* dst = (float4*)(out + ((size_t)b * TT + idx) * DD);
    const float4* src = (const float4*)(g_h + (size_t)row * DD);
    for (int i = threadIdx.x; i < DD / 4; i += blockDim.x) {
        float4 d = dst[i], s = src[i];
        d.x += g * s.x; d.y += g * s.y; d.z += g * s.z; d.w += g * s.w;
        dst[i] = d;
    }
}

// ---------------- host launcher ----------------
extern "C" void kernel_launch(void* const* d_in, const int* in_sizes, int n_in,
                              void* d_out, int out_size) {
    const float* x        = (const float*)d_in[0];
    const float* router_w = (const float*)d_in[1];
    const float* router_b = (const float*)d_in[2];
    const float* ln1_w    = (const float*)d_in[3];
    const float* ln1_b    = (const float*)d_in[4];
    const float* wqkv     = (const float*)d_in[5];
    const float* wo       = (const float*)d_in[6];
    const float* ln2_w    = (const float*)d_in[7];
    const float* ln2_b    = (const float*)d_in[8];
    const float* w1       = (const float*)d_in[9];
    const float* w2       = (const float*)d_in[10];
    float* out = (float*)d_out;

    float *p_h;
    __half *p_y, *p_qkv, *p_ff;
    __half *p_wqkvt, *p_w1t, *p_w2t, *p_wot;
    cudaGetSymbolAddress((void**)&p_h, g_h);
    cudaGetSymbolAddress((void**)&p_y, g_y);
    cudaGetSymbolAddress((void**)&p_qkv, g_qkv);
    cudaGetSymbolAddress((void**)&p_ff, g_ff);
    cudaGetSymbolAddress((void**)&p_wqkvt, g_wqkvt);
    cudaGetSymbolAddress((void**)&p_w1t, g_w1t);
    cudaGetSymbolAddress((void**)&p_w2t, g_w2t);
    cudaGetSymbolAddress((void**)&p_wot, g_wot);

    const int FSMEM = 5 * 128 * FPITCH * 2;   // 92160 B
    cudaFuncSetAttribute(flash_kernel, cudaFuncAttributeMaxDynamicSharedMemorySize, FSMEM);

    router_kernel<<<BB * TT, 256>>>(x, router_w, router_b);
    topk_kernel<<<BB, 1024>>>();
    gather_kernel<<<MR, 256>>>(x);

    // pre-transpose + fp16-convert weights: W[K,N] -> Wt[N,K]
    dim3 tb(32, 8);
    transpose_w<<<dim3(3 * DD / 32, DD / 32, LL), tb>>>(
        wqkv, p_wqkvt, DD, 3 * DD, (long long)DD * 3 * DD, (long long)3 * DD * DD);
    transpose_w<<<dim3(FF / 32, DD / 32, LL), tb>>>(
        w1, p_w1t, DD, FF, (long long)DD * FF, (long long)FF * DD);
    transpose_w<<<dim3(DD / 32, FF / 32, LL), tb>>>(
        w2, p_w2t, FF, DD, (long long)FF * DD, (long long)DD * FF);
    transpose_w<<<dim3(DD / 32, DD / 32, LL), tb>>>(
        wo, p_wot, DD, DD, (long long)DD * DD, (long long)DD * DD);

    for (int l = 0; l < LL; l++) {
        // --- attention sub-block ---
        ln_kernel<<<MR, 256>>>(p_h, ln1_w + l * DD, ln1_b + l * DD, p_y);

        // qkv = y @ Wqkv^T  (fp16 out)
        h_gemm<<<dim3(3 * DD / 128, MR / 128, 1), 256>>>(
            p_y, p_wqkvt + (size_t)l * 3 * DD * DD, p_h, p_qkv,
            DD, DD, DD, 3 * DD, 1.f, 0, 0, 1);

        // fused attention -> y (fp16)
        flash_kernel<<<dim3(KC / 128, BB * HH), 256, FSMEM>>>(p_qkv, p_y);

        // h += O @ Wo^T (fp32 out + residual)
        h_gemm<<<dim3(DD / 128, MR / 128, 1), 256>>>(
            p_y, p_wot + (size_t)l * DD * DD, p_h, p_h,
            DD, DD, DD, DD, 1.f, 1, 0, 0);

        // --- MLP sub-block ---
        ln_kernel<<<MR, 256>>>(p_h, ln2_w + l * DD, ln2_b + l * DD, p_y);

        h_gemm<<<dim3(FF / 128, MR / 128, 1), 256>>>(
            p_y, p_w1t + (size_t)l * FF * DD, p_h, p_ff,
            DD, DD, DD, FF, 1.f, 0, 1, 1);

        h_gemm<<<dim3(DD / 128, MR / 128, 1), 256>>>(
            p_ff, p_w2t + (size_t)l * DD * FF, p_h, p_h,
            FF, FF, FF, DD, 1.f, 1, 0, 0);
    }

    cudaMemcpyAsync(out, x, (size_t)BB * TT * DD * sizeof(float),
                    cudaMemcpyDeviceToDevice, 0);
    scatter_kernel<<<MR, 256>>>(out);
}